// round 15
// baseline (speedup 1.0000x reference)
#include <cuda_runtime.h>
#include <cuda_fp16.h>
#include <cstdint>

#define BB 32
#define LL 1024
#define HH 128
#define SK 136              // smem row stride in halfs (conflict-free ldmatrix)
#define SSTRIDE (3 * 128 * SK)  // halfs per k3 stage: E | Wb | Wa

// ---------------- scratch (__device__ globals) ------------------------------
__device__ __half g_E16[(size_t)BB * LL * LL];   // exp(masked scores), 64 MB
__device__ __half g_a16[(size_t)BB * LL * HH];
__device__ __half g_b16[(size_t)BB * LL * HH];
__device__ __half g_bT16[(size_t)BB * HH * LL];  // b^T [b,d,m]
__device__ __half g_aT16[(size_t)BB * HH * LL];  // a^T [b,d,m]
__device__ __half g_aTs16[(size_t)BB * HH * LL]; // (a*invC)^T [b,d,m]
__device__ float  g_Rp[8][BB * LL];              // per-m-tile partial row sums
__device__ float  g_Cp[4][BB * LL];              // per-l-tile partial col sums
__device__ float  g_mbp[8][BB * HH];             // per-m-tile partial meanb
__device__ float  g_vp[8][BB * HH];              // per-m-tile partial vmask
__device__ float  g_C[BB * LL];

// ---------------- PTX helpers ----------------------------------------------
__device__ __forceinline__ uint32_t smem_u32(const void* p) {
    uint32_t a;
    asm("{ .reg .u64 t; cvta.to.shared.u64 t, %1; cvt.u32.u64 %0, t; }"
        : "=r"(a) : "l"(p));
    return a;
}
#define LDSM4(R0, R1, R2, R3, ADDR)                                            \
    asm volatile("ldmatrix.sync.aligned.m8n8.x4.shared.b16 {%0,%1,%2,%3}, [%4];" \
                 : "=r"(R0), "=r"(R1), "=r"(R2), "=r"(R3) : "r"(ADDR))
#define CP_ASYNC16(DST, SRC)                                                   \
    asm volatile("cp.async.cg.shared.global [%0], [%1], 16;" :: "r"(DST), "l"(SRC))
#define CP_COMMIT() asm volatile("cp.async.commit_group;")

__device__ __forceinline__ void mma_16816(float* c, const uint32_t* a,
                                          uint32_t b0, uint32_t b1) {
    asm volatile(
        "mma.sync.aligned.m16n8k16.row.col.f32.f16.f16.f32 "
        "{%0,%1,%2,%3},{%4,%5,%6,%7},{%8,%9},{%0,%1,%2,%3};"
        : "+f"(c[0]), "+f"(c[1]), "+f"(c[2]), "+f"(c[3])
        : "r"(a[0]), "r"(a[1]), "r"(a[2]), "r"(a[3]), "r"(b0), "r"(b1));
}

// ---------------- conv_all: fp16 convert + both transposes + meanb ---------
__global__ __launch_bounds__(256) void conv_all(const float* __restrict__ a,
                                                const float* __restrict__ b) {
    extern __shared__ char dsm[];
    __half* ta = (__half*)dsm;            // 128 x SK
    __half* tb = ta + 128 * SK;
    const int mt = blockIdx.x * 128, batch = blockIdx.y;
    const int t = threadIdx.x;
    const int r = t >> 1, dh = (t & 1) * 64;
    const size_t grow = (size_t)(batch * LL + mt + r) * HH + dh;
    const float4* as = (const float4*)(a + grow);
    const float4* bs = (const float4*)(b + grow);
    uint4 abuf[8], bbuf[8];
#pragma unroll
    for (int j = 0; j < 8; j++) {
        float4 va0 = as[2 * j], va1 = as[2 * j + 1];
        float4 vb0 = bs[2 * j], vb1 = bs[2 * j + 1];
        uint4 pa, pb;
        ((__half2*)&pa)[0] = __floats2half2_rn(va0.x, va0.y);
        ((__half2*)&pa)[1] = __floats2half2_rn(va0.z, va0.w);
        ((__half2*)&pa)[2] = __floats2half2_rn(va1.x, va1.y);
        ((__half2*)&pa)[3] = __floats2half2_rn(va1.z, va1.w);
        ((__half2*)&pb)[0] = __floats2half2_rn(vb0.x, vb0.y);
        ((__half2*)&pb)[1] = __floats2half2_rn(vb0.z, vb0.w);
        ((__half2*)&pb)[2] = __floats2half2_rn(vb1.x, vb1.y);
        ((__half2*)&pb)[3] = __floats2half2_rn(vb1.z, vb1.w);
        abuf[j] = pa; bbuf[j] = pb;
        ((uint4*)(g_a16 + grow))[j] = pa;
        ((uint4*)(g_b16 + grow))[j] = pb;
    }
#pragma unroll
    for (int j = 0; j < 8; j++) {
        const __half* ha = (const __half*)&abuf[j];
        const __half* hb = (const __half*)&bbuf[j];
#pragma unroll
        for (int k = 0; k < 8; k++) {
            ta[(dh + j * 8 + k) * SK + r] = ha[k];
            tb[(dh + j * 8 + k) * SK + r] = hb[k];
        }
    }
    __syncthreads();
    const int d = t >> 1, mh = (t & 1) * 64;
    const size_t trow = (size_t)(batch * HH + d) * LL + mt + mh;
    const uint4* sa = (const uint4*)(ta + d * SK + mh);
    const uint4* sb = (const uint4*)(tb + d * SK + mh);
#pragma unroll
    for (int q = 0; q < 8; q++) {
        ((uint4*)(g_aT16 + trow))[q] = sa[q];
        ((uint4*)(g_bT16 + trow))[q] = sb[q];
    }
    if (t < 128) {
        const __half* rowp = tb + t * SK;
        float s = 0.f;
#pragma unroll
        for (int q = 0; q < 16; q++) {
            uint4 v = *(const uint4*)(rowp + q * 8);
            const __half2* h = (const __half2*)&v;
#pragma unroll
            for (int k = 0; k < 4; k++) {
                float2 f = __half22float2(h[k]);
                s += f.x + f.y;
            }
        }
        g_mbp[blockIdx.x][batch * HH + t] = s;
    }
}

// ---------------- K1: 256l x 128m, 512 thr, cp.async k-chunk pipeline ------
__global__ __launch_bounds__(512) void k1_scores(const int* __restrict__ ma,
                                                 const int* __restrict__ mb,
                                                 const float* __restrict__ tptr) {
    extern __shared__ char dsm[];
    __half* As = (__half*)dsm;            // 256 x SK (A tile, later E staging)
    __half* Bs = As + 256 * SK;           // 128 x SK
    int*   cms = (int*)(Bs + 128 * SK);   // 128 ints
    float* rs  = (float*)(cms + 128);     // [4][256]
    float* cs  = rs + 4 * 256;            // [4][128]

    const int batch = blockIdx.z, l0 = blockIdx.y * 256, m0 = blockIdx.x * 128;
    const int t = threadIdx.x, lane = t & 31, w = t >> 5;
    const int wr = w >> 2, wc = w & 3;
    const uint32_t sbase = smem_u32(As);

    if (t < 128) cms[t] = mb[batch * LL + m0 + t];

    // cp.async pipeline: two k-chunks of 64 halfs (128 B per row each)
    {
        const int arow = t >> 1, akk = (t & 1) * 32;   // A: 2 thr/row, 32 halfs each
        const int brow = t >> 2, bkk = (t & 3) * 16;   // B: 4 thr/row, 16 halfs each
        const __half* aq = g_a16 + (size_t)(batch * LL + l0 + arow) * HH + akk;
        const __half* bq = g_b16 + (size_t)(batch * LL + m0 + brow) * HH + bkk;
        const uint32_t adst = sbase + (arow * SK + akk) * 2;
        const uint32_t bdst = sbase + (256 * SK + brow * SK + bkk) * 2;
#pragma unroll
        for (int ck = 0; ck < 2; ck++) {
            const int ko = ck * 64;
#pragma unroll
            for (int j = 0; j < 4; j++)
                CP_ASYNC16(adst + (ko + j * 8) * 2, aq + ko + j * 8);
#pragma unroll
            for (int j = 0; j < 2; j++)
                CP_ASYNC16(bdst + (ko + j * 8) * 2, bq + ko + j * 8);
            CP_COMMIT();
        }
    }

    float acc[4][4][4];
#pragma unroll
    for (int i = 0; i < 4; i++)
#pragma unroll
        for (int j = 0; j < 4; j++)
#pragma unroll
            for (int k = 0; k < 4; k++) acc[i][j][k] = 0.f;

    const uint32_t aaddr = sbase + ((wr * 64 + (lane & 15)) * SK + (lane >> 4) * 8) * 2;
    const uint32_t baddr = sbase + (256 * SK + (wc * 32 + (lane & 15)) * SK + (lane >> 4) * 8) * 2;

#pragma unroll
    for (int half = 0; half < 2; half++) {
        if (half == 0) { asm volatile("cp.async.wait_group 1;"); }
        else           { asm volatile("cp.async.wait_group 0;"); }
        __syncthreads();
#pragma unroll
        for (int ci = 0; ci < 4; ci++) {
            const int c = half * 4 + ci;
            uint32_t av[4][4], bv[2][4];
#pragma unroll
            for (int mi = 0; mi < 4; mi++)
                LDSM4(av[mi][0], av[mi][1], av[mi][2], av[mi][3],
                      aaddr + (mi * 16 * SK + c * 16) * 2);
#pragma unroll
            for (int nh = 0; nh < 2; nh++)
                LDSM4(bv[nh][0], bv[nh][1], bv[nh][2], bv[nh][3],
                      baddr + (nh * 16 * SK + c * 16) * 2);
#pragma unroll
            for (int mi = 0; mi < 4; mi++)
#pragma unroll
                for (int nj = 0; nj < 4; nj++)
                    mma_16816(acc[mi][nj], av[mi], bv[nj >> 1][nj & 1], bv[nj >> 1][(nj & 1) + 2]);
        }
    }
    __syncthreads();     // As re-used as E staging below

    const float temp = *tptr;
    float cloc[4][2];
#pragma unroll
    for (int nj = 0; nj < 4; nj++) { cloc[nj][0] = 0.f; cloc[nj][1] = 0.f; }

#pragma unroll
    for (int mi = 0; mi < 4; mi++) {
        const int r0 = wr * 64 + mi * 16 + (lane >> 2);
        const int gr0 = batch * LL + l0 + r0;
        const int rm0 = ma[gr0], rm1 = ma[gr0 + 8];
        __half* es0 = As + r0 * SK;
        float r0sum = 0.f, r1sum = 0.f;
#pragma unroll
        for (int nj = 0; nj < 4; nj++) {
            const int col = wc * 32 + nj * 8 + (lane & 3) * 2;
            const int cm0 = cms[col], cm1 = cms[col + 1];
            float* cc = acc[mi][nj];
            const float v00 = (rm0 && cm0) ? __expf(cc[0] * temp) : 0.f;
            const float v01 = (rm0 && cm1) ? __expf(cc[1] * temp) : 0.f;
            const float v10 = (rm1 && cm0) ? __expf(cc[2] * temp) : 0.f;
            const float v11 = (rm1 && cm1) ? __expf(cc[3] * temp) : 0.f;
            *(__half2*)(es0 + col)          = __floats2half2_rn(v00, v01);
            *(__half2*)(es0 + 8 * SK + col) = __floats2half2_rn(v10, v11);
            r0sum += v00 + v01; r1sum += v10 + v11;
            cloc[nj][0] += v00 + v10; cloc[nj][1] += v01 + v11;
        }
        r0sum += __shfl_xor_sync(0xffffffffu, r0sum, 1);
        r0sum += __shfl_xor_sync(0xffffffffu, r0sum, 2);
        r1sum += __shfl_xor_sync(0xffffffffu, r1sum, 1);
        r1sum += __shfl_xor_sync(0xffffffffu, r1sum, 2);
        if ((lane & 3) == 0) {
            rs[wc * 256 + r0] = r0sum;
            rs[wc * 256 + r0 + 8] = r1sum;
        }
    }
#pragma unroll
    for (int nj = 0; nj < 4; nj++)
#pragma unroll
        for (int k = 0; k < 2; k++) {
            float v = cloc[nj][k];
            v += __shfl_xor_sync(0xffffffffu, v, 4);
            v += __shfl_xor_sync(0xffffffffu, v, 8);
            v += __shfl_xor_sync(0xffffffffu, v, 16);
            if (lane < 4) cs[wr * 128 + wc * 32 + nj * 8 + lane * 2 + k] = v;
        }
    __syncthreads();

    // coalesced E write-out: warp = 8 rows x 256B contiguous
    {
        const int er = t >> 2;            // 0..127
        const int ec = (t & 3) * 32;      // half offset in row
#pragma unroll
        for (int g = 0; g < 2; g++) {
            const int row = g * 128 + er;
            const uint4* srow = (const uint4*)(As + row * SK + ec);
            uint4* gdst = (uint4*)(g_E16 + (size_t)(batch * LL + l0 + row) * LL + m0 + ec);
#pragma unroll
            for (int q = 0; q < 4; q++) gdst[q] = srow[q];
        }
    }
    if (t < 256) {
        g_Rp[blockIdx.x][batch * LL + l0 + t] =
            rs[t] + rs[256 + t] + rs[512 + t] + rs[768 + t];
    } else if (t < 384) {
        const int i = t - 256;
        g_Cp[blockIdx.y][batch * LL + m0 + i] =
            cs[i] + cs[128 + i] + cs[256 + i] + cs[384 + i];
    }
}

// ---------------- fused_C: C-reduce + invC + aTs scale + vmask partials ----
__global__ __launch_bounds__(256) void fused_C() {
    __shared__ float sInv[128];
    const int mt = blockIdx.x * 128, batch = blockIdx.y;
    const int t = threadIdx.x;
    if (t < 128) {
        float s = 0.f;
#pragma unroll
        for (int q = 0; q < 4; q++) s += g_Cp[q][batch * LL + mt + t];
        g_C[batch * LL + mt + t] = s;
        sInv[t] = (s > 0.f) ? (1.f / s) : 0.f;
    }
    __syncthreads();
    const int d = t >> 1, mh = (t & 1) * 64;
    const size_t off = (size_t)(batch * HH + d) * LL + mt + mh;
    const uint4* src = (const uint4*)(g_aT16 + off);
    uint4* dst = (uint4*)(g_aTs16 + off);
    float vpart = 0.f;
#pragma unroll
    for (int q = 0; q < 8; q++) {
        uint4 v = src[q];
        __half2* h = (__half2*)&v;
#pragma unroll
        for (int k = 0; k < 4; k++) {
            float2 f = __half22float2(h[k]);
            const int ml = mh + q * 8 + k * 2;
            const float i0 = sInv[ml], i1 = sInv[ml + 1];
            vpart += (i0 == 0.f ? f.x : 0.f) + (i1 == 0.f ? f.y : 0.f);
            h[k] = __floats2half2_rn(f.x * i0, f.y * i1);
        }
        dst[q] = v;
    }
    vpart += __shfl_xor_sync(0xffffffffu, vpart, 1);
    if ((t & 1) == 0) g_vp[blockIdx.x][batch * HH + d] = vpart;
}

// ---------------- K3: dual feature GEMMs, 512 thr, 4x4 warp grid -----------
__global__ __launch_bounds__(512) void k3_feat(float* __restrict__ out) {
    extern __shared__ char dsm[];
    __half* S = (__half*)dsm;                       // 2 stages x SSTRIDE halfs
    float* smeanb = (float*)(S + 2 * SSTRIDE);
    float* svmask = smeanb + 128;
    float* sR     = svmask + 128;                   // 128 floats

    const int batch = blockIdx.y, l0 = blockIdx.x * 128;
    const int t = threadIdx.x, lane = t & 31, w = t >> 5;
    const int wr = w >> 2, wc = w & 3;              // 4x4 warp grid: 32l x 32d
    const uint32_t sbase = smem_u32(S);

    if (t < 128) {
        float s = 0.f;
#pragma unroll
        for (int q = 0; q < 8; q++) s += g_Rp[q][batch * LL + l0 + t];
        sR[t] = s;
    } else if (t < 256) {
        const int d = t - 128;
        float sb = 0.f, sv = 0.f;
#pragma unroll
        for (int q = 0; q < 8; q++) {
            sb += g_mbp[q][batch * HH + d];
            sv += g_vp[q][batch * HH + d];
        }
        smeanb[d] = sb;
        svmask[d] = sv;
    }

    const int row = t >> 2, kh = (t & 3) * 32;
    const __half* eg = g_E16   + ((size_t)(batch * LL + l0 + row)) * LL + kh;
    const __half* bg = g_bT16  + ((size_t)(batch * HH + row)) * LL + kh;
    const __half* ag = g_aTs16 + ((size_t)(batch * HH + row)) * LL + kh;
    const uint32_t sdst = sbase + (row * SK + kh) * 2;

    {
#pragma unroll
        for (int j = 0; j < 4; j++) {
            CP_ASYNC16(sdst + j * 16,                    eg + j * 8);
            CP_ASYNC16(sdst + 128 * SK * 2 + j * 16,     bg + j * 8);
            CP_ASYNC16(sdst + 256 * SK * 2 + j * 16,     ag + j * 8);
        }
        CP_COMMIT();
    }

    float acc_a[2][4][4], acc_b[2][4][4];
#pragma unroll
    for (int i = 0; i < 2; i++)
#pragma unroll
        for (int j = 0; j < 4; j++)
#pragma unroll
            for (int k = 0; k < 4; k++) { acc_a[i][j][k] = 0.f; acc_b[i][j][k] = 0.f; }

    const uint32_t eoff = sbase + ((wr * 32 + (lane & 15)) * SK + (lane >> 4) * 8) * 2;
    const uint32_t woff = sbase + ((wc * 32 + (lane & 15)) * SK + (lane >> 4) * 8) * 2;

    for (int mc = 0; mc < 8; mc++) {
        if (mc < 7) {
            const uint32_t nb = ((mc + 1) & 1) * SSTRIDE * 2;
            const int m1 = (mc + 1) * 128;
#pragma unroll
            for (int j = 0; j < 4; j++) {
                CP_ASYNC16(sdst + nb + j * 16,                eg + m1 + j * 8);
                CP_ASYNC16(sdst + nb + 128 * SK * 2 + j * 16, bg + m1 + j * 8);
                CP_ASYNC16(sdst + nb + 256 * SK * 2 + j * 16, ag + m1 + j * 8);
            }
            CP_COMMIT();
            asm volatile("cp.async.wait_group 1;");
        } else {
            asm volatile("cp.async.wait_group 0;");
        }
        __syncthreads();

        const uint32_t sb_ = (mc & 1) * SSTRIDE * 2;
        const uint32_t eaddr = eoff + sb_;
        const uint32_t baddr = woff + sb_ + 128 * SK * 2;
        const uint32_t aaddr = woff + sb_ + 256 * SK * 2;
#pragma unroll
        for (int c = 0; c < 8; c++) {
            uint32_t ev[2][4], bvb[2][4], bva[2][4];
#pragma unroll
            for (int mi = 0; mi < 2; mi++)
                LDSM4(ev[mi][0], ev[mi][1], ev[mi][2], ev[mi][3],
                      eaddr + (mi * 16 * SK + c * 16) * 2);
#pragma unroll
            for (int nh = 0; nh < 2; nh++) {
                LDSM4(bvb[nh][0], bvb[nh][1], bvb[nh][2], bvb[nh][3],
                      baddr + (nh * 16 * SK + c * 16) * 2);
                LDSM4(bva[nh][0], bva[nh][1], bva[nh][2], bva[nh][3],
                      aaddr + (nh * 16 * SK + c * 16) * 2);
            }
#pragma unroll
            for (int mi = 0; mi < 2; mi++)
#pragma unroll
                for (int nj = 0; nj < 4; nj++) {
                    mma_16816(acc_a[mi][nj], ev[mi], bvb[nj >> 1][nj & 1], bvb[nj >> 1][(nj & 1) + 2]);
                    mma_16816(acc_b[mi][nj], ev[mi], bva[nj >> 1][nj & 1], bva[nj >> 1][(nj & 1) + 2]);
                }
        }
        __syncthreads();
    }

    const size_t FB = (size_t)BB * LL * HH;
    const float INV = 1.f / 1024.f;
#pragma unroll
    for (int mi = 0; mi < 2; mi++) {
        const int r0 = wr * 32 + mi * 16 + (lane >> 2);
        const int g0 = batch * LL + l0 + r0;
        const float rv0 = sR[r0], rv1 = sR[r0 + 8];
        const float sc0 = (rv0 > 0.f) ? (1.f / rv0) : 0.f;
        const float sc1 = (rv1 > 0.f) ? (1.f / rv1) : 0.f;
        const bool u0 = !(rv0 > 0.f), u1 = !(rv1 > 0.f);
        float* oa0 = out + (size_t)g0 * HH;
        float* oa1 = oa0 + (size_t)8 * HH;
        float* ob0 = oa0 + FB;
        float* ob1 = oa1 + FB;
#pragma unroll
        for (int nj = 0; nj < 4; nj++) {
            const int col = wc * 32 + nj * 8 + (lane & 3) * 2;
            const float mb0 = smeanb[col] * INV, mb1 = smeanb[col + 1] * INV;
            const float vm0 = svmask[col] * INV, vm1 = svmask[col + 1] * INV;
            float* ca = acc_a[mi][nj];
            float* cb = acc_b[mi][nj];
            float2 va0 = { u0 ? mb0 : ca[0] * sc0, u0 ? mb1 : ca[1] * sc0 };
            float2 va1 = { u1 ? mb0 : ca[2] * sc1, u1 ? mb1 : ca[3] * sc1 };
            float2 vb0 = { cb[0] + vm0, cb[1] + vm1 };
            float2 vb1 = { cb[2] + vm0, cb[3] + vm1 };
            *(float2*)(oa0 + col) = va0;
            *(float2*)(oa1 + col) = va1;
            *(float2*)(ob0 + col) = vb0;
            *(float2*)(ob1 + col) = vb1;
        }
    }
}

// ---------------- launch ----------------------------------------------------
extern "C" void kernel_launch(void* const* d_in, const int* in_sizes, int n_in,
                              void* d_out, int out_size) {
    const float* a    = (const float*)d_in[0];
    const float* b    = (const float*)d_in[1];
    const int*   ma   = (const int*)d_in[2];
    const int*   mb   = (const int*)d_in[3];
    const float* temp = (const float*)d_in[4];
    float* out = (float*)d_out;

    const int CV_SMEM = 2 * 128 * SK * 2;                        // 69632
    const int K1_SMEM = 384 * SK * 2 + 512 + 4096 + 2048 + 1024; // 112128
    const int K3_SMEM = 2 * SSTRIDE * 2 + 2048;                  // 210944
    cudaFuncSetAttribute(conv_all,  cudaFuncAttributeMaxDynamicSharedMemorySize, CV_SMEM);
    cudaFuncSetAttribute(k1_scores, cudaFuncAttributeMaxDynamicSharedMemorySize, K1_SMEM);
    cudaFuncSetAttribute(k3_feat,   cudaFuncAttributeMaxDynamicSharedMemorySize, K3_SMEM);

    conv_all<<<dim3(8, BB), 256, CV_SMEM>>>(a, b);             // launch 0
    k1_scores<<<dim3(8, 4, BB), 512, K1_SMEM>>>(ma, mb, temp); // launch 1
    fused_C<<<dim3(8, BB), 256>>>();                           // launch 2
    k3_feat<<<dim3(8, BB), 512, K3_SMEM>>>(out);               // launch 3 (ncu slot)
}

// round 16
// speedup vs baseline: 1.1054x; 1.1054x over previous
#include <cuda_runtime.h>
#include <cuda_fp16.h>
#include <cstdint>

#define BB 32
#define LL 1024
#define HH 128
#define SK 136              // smem row stride in halfs (conflict-free ldmatrix)
#define SSTRIDE (3 * 128 * SK)  // halfs per k3 stage: E | Wb | Wa

// ---------------- scratch (__device__ globals) ------------------------------
__device__ __half g_E16[(size_t)BB * LL * LL];   // exp(masked scores), 64 MB
__device__ __half g_a16[(size_t)BB * LL * HH];
__device__ __half g_b16[(size_t)BB * LL * HH];
__device__ __half g_bT16[(size_t)BB * HH * LL];  // b^T [b,d,m]
__device__ __half g_aT16[(size_t)BB * HH * LL];  // a^T [b,d,m]
__device__ __half g_aTs16[(size_t)BB * HH * LL]; // (a*invC)^T [b,d,m]
__device__ float  g_Rp[8][BB * LL];              // per-m-tile partial row sums
__device__ float  g_Cp[4][BB * LL];              // per-l-tile partial col sums
__device__ float  g_mbp[8][BB * HH];             // per-m-tile partial meanb
__device__ float  g_vp[8][BB * HH];              // per-m-tile partial vmask
__device__ float  g_C[BB * LL];

// ---------------- PTX helpers ----------------------------------------------
__device__ __forceinline__ uint32_t smem_u32(const void* p) {
    uint32_t a;
    asm("{ .reg .u64 t; cvta.to.shared.u64 t, %1; cvt.u32.u64 %0, t; }"
        : "=r"(a) : "l"(p));
    return a;
}
#define LDSM4(R0, R1, R2, R3, ADDR)                                            \
    asm volatile("ldmatrix.sync.aligned.m8n8.x4.shared.b16 {%0,%1,%2,%3}, [%4];" \
                 : "=r"(R0), "=r"(R1), "=r"(R2), "=r"(R3) : "r"(ADDR))
#define CP_ASYNC16(DST, SRC)                                                   \
    asm volatile("cp.async.cg.shared.global [%0], [%1], 16;" :: "r"(DST), "l"(SRC))
#define CP_COMMIT() asm volatile("cp.async.commit_group;")

__device__ __forceinline__ void mma_16816(float* c, const uint32_t* a,
                                          uint32_t b0, uint32_t b1) {
    asm volatile(
        "mma.sync.aligned.m16n8k16.row.col.f32.f16.f16.f32 "
        "{%0,%1,%2,%3},{%4,%5,%6,%7},{%8,%9},{%0,%1,%2,%3};"
        : "+f"(c[0]), "+f"(c[1]), "+f"(c[2]), "+f"(c[3])
        : "r"(a[0]), "r"(a[1]), "r"(a[2]), "r"(a[3]), "r"(b0), "r"(b1));
}

// ---------------- conv16: fp32 -> fp16 elementwise (a and b) ---------------
__global__ __launch_bounds__(256) void conv16(const float* __restrict__ a,
                                              const float* __restrict__ b) {
    const size_t i = (size_t)blockIdx.x * 256 + threadIdx.x;  // 8-half index
    const float4* af = (const float4*)a;
    const float4* bf = (const float4*)b;
    float4 va0 = af[2 * i], va1 = af[2 * i + 1];
    float4 vb0 = bf[2 * i], vb1 = bf[2 * i + 1];
    uint4 pa, pb;
    ((__half2*)&pa)[0] = __floats2half2_rn(va0.x, va0.y);
    ((__half2*)&pa)[1] = __floats2half2_rn(va0.z, va0.w);
    ((__half2*)&pa)[2] = __floats2half2_rn(va1.x, va1.y);
    ((__half2*)&pa)[3] = __floats2half2_rn(va1.z, va1.w);
    ((__half2*)&pb)[0] = __floats2half2_rn(vb0.x, vb0.y);
    ((__half2*)&pb)[1] = __floats2half2_rn(vb0.z, vb0.w);
    ((__half2*)&pb)[2] = __floats2half2_rn(vb1.x, vb1.y);
    ((__half2*)&pb)[3] = __floats2half2_rn(vb1.z, vb1.w);
    ((uint4*)g_a16)[i] = pa;
    ((uint4*)g_b16)[i] = pb;
}

// ---------------- transpose_ab: z=0 -> a, z=1 -> b (+ meanb partials) ------
__global__ __launch_bounds__(256) void transpose_ab() {
    __shared__ __half tt[128][SK];
    const int mt = blockIdx.x * 128, batch = blockIdx.y;
    const int which = blockIdx.z;     // 0 = a, 1 = b
    const int t = threadIdx.x;
    const __half* gsrc = which ? g_b16 : g_a16;
    __half* gdstT      = which ? g_bT16 : g_aT16;
    const int r = t >> 1, dh = (t & 1) * 64;
    const uint4* src = (const uint4*)(gsrc + (size_t)(batch * LL + mt + r) * HH + dh);
#pragma unroll
    for (int j = 0; j < 8; j++) {
        uint4 v = src[j];
        const __half* h = (const __half*)&v;
#pragma unroll
        for (int k = 0; k < 8; k++) tt[dh + j * 8 + k][r] = h[k];
    }
    __syncthreads();
    const int d = t >> 1, mh = (t & 1) * 64;
    uint4* dst = (uint4*)(gdstT + (size_t)(batch * HH + d) * LL + mt + mh);
    const uint4* srow = (const uint4*)&tt[d][mh];
#pragma unroll
    for (int q = 0; q < 8; q++) dst[q] = srow[q];
    if (which && t < 128) {
        const __half* rowp = &tt[t][0];
        float s = 0.f;
#pragma unroll
        for (int q = 0; q < 16; q++) {
            uint4 v = *(const uint4*)(rowp + q * 8);
            const __half2* h = (const __half2*)&v;
#pragma unroll
            for (int k = 0; k < 4; k++) {
                float2 f = __half22float2(h[k]);
                s += f.x + f.y;
            }
        }
        g_mbp[blockIdx.x][batch * HH + t] = s;
    }
}

// ---------------- K1: 256l x 128m, 512 thr, cp.async k-chunk pipeline ------
__global__ __launch_bounds__(512) void k1_scores(const int* __restrict__ ma,
                                                 const int* __restrict__ mb,
                                                 const float* __restrict__ tptr) {
    extern __shared__ char dsm[];
    __half* As = (__half*)dsm;            // 256 x SK (A tile, later E staging)
    __half* Bs = As + 256 * SK;           // 128 x SK
    int*   cms = (int*)(Bs + 128 * SK);   // 128 ints
    float* rs  = (float*)(cms + 128);     // [4][256]
    float* cs  = rs + 4 * 256;            // [4][128]

    const int batch = blockIdx.z, l0 = blockIdx.y * 256, m0 = blockIdx.x * 128;
    const int t = threadIdx.x, lane = t & 31, w = t >> 5;
    const int wr = w >> 2, wc = w & 3;
    const uint32_t sbase = smem_u32(As);

    if (t < 128) cms[t] = mb[batch * LL + m0 + t];

    // cp.async pipeline: two k-chunks of 64 halfs (128 B per row each)
    {
        const int arow = t >> 1, akk = (t & 1) * 32;   // A: 2 thr/row, 32 halfs each
        const int brow = t >> 2, bkk = (t & 3) * 16;   // B: 4 thr/row, 16 halfs each
        const __half* aq = g_a16 + (size_t)(batch * LL + l0 + arow) * HH + akk;
        const __half* bq = g_b16 + (size_t)(batch * LL + m0 + brow) * HH + bkk;
        const uint32_t adst = sbase + (arow * SK + akk) * 2;
        const uint32_t bdst = sbase + (256 * SK + brow * SK + bkk) * 2;
#pragma unroll
        for (int ck = 0; ck < 2; ck++) {
            const int ko = ck * 64;
#pragma unroll
            for (int j = 0; j < 4; j++)
                CP_ASYNC16(adst + (ko + j * 8) * 2, aq + ko + j * 8);
#pragma unroll
            for (int j = 0; j < 2; j++)
                CP_ASYNC16(bdst + (ko + j * 8) * 2, bq + ko + j * 8);
            CP_COMMIT();
        }
    }

    float acc[4][4][4];
#pragma unroll
    for (int i = 0; i < 4; i++)
#pragma unroll
        for (int j = 0; j < 4; j++)
#pragma unroll
            for (int k = 0; k < 4; k++) acc[i][j][k] = 0.f;

    const uint32_t aaddr = sbase + ((wr * 64 + (lane & 15)) * SK + (lane >> 4) * 8) * 2;
    const uint32_t baddr = sbase + (256 * SK + (wc * 32 + (lane & 15)) * SK + (lane >> 4) * 8) * 2;

#pragma unroll
    for (int half = 0; half < 2; half++) {
        if (half == 0) { asm volatile("cp.async.wait_group 1;"); }
        else           { asm volatile("cp.async.wait_group 0;"); }
        __syncthreads();
#pragma unroll
        for (int ci = 0; ci < 4; ci++) {
            const int c = half * 4 + ci;
            uint32_t av[4][4], bv[2][4];
#pragma unroll
            for (int mi = 0; mi < 4; mi++)
                LDSM4(av[mi][0], av[mi][1], av[mi][2], av[mi][3],
                      aaddr + (mi * 16 * SK + c * 16) * 2);
#pragma unroll
            for (int nh = 0; nh < 2; nh++)
                LDSM4(bv[nh][0], bv[nh][1], bv[nh][2], bv[nh][3],
                      baddr + (nh * 16 * SK + c * 16) * 2);
#pragma unroll
            for (int mi = 0; mi < 4; mi++)
#pragma unroll
                for (int nj = 0; nj < 4; nj++)
                    mma_16816(acc[mi][nj], av[mi], bv[nj >> 1][nj & 1], bv[nj >> 1][(nj & 1) + 2]);
        }
    }
    __syncthreads();     // As re-used as E staging below

    const float temp = *tptr;
    float cloc[4][2];
#pragma unroll
    for (int nj = 0; nj < 4; nj++) { cloc[nj][0] = 0.f; cloc[nj][1] = 0.f; }

#pragma unroll
    for (int mi = 0; mi < 4; mi++) {
        const int r0 = wr * 64 + mi * 16 + (lane >> 2);
        const int gr0 = batch * LL + l0 + r0;
        const int rm0 = ma[gr0], rm1 = ma[gr0 + 8];
        __half* es0 = As + r0 * SK;
        float r0sum = 0.f, r1sum = 0.f;
#pragma unroll
        for (int nj = 0; nj < 4; nj++) {
            const int col = wc * 32 + nj * 8 + (lane & 3) * 2;
            const int cm0 = cms[col], cm1 = cms[col + 1];
            float* cc = acc[mi][nj];
            const float v00 = (rm0 && cm0) ? __expf(cc[0] * temp) : 0.f;
            const float v01 = (rm0 && cm1) ? __expf(cc[1] * temp) : 0.f;
            const float v10 = (rm1 && cm0) ? __expf(cc[2] * temp) : 0.f;
            const float v11 = (rm1 && cm1) ? __expf(cc[3] * temp) : 0.f;
            *(__half2*)(es0 + col)          = __floats2half2_rn(v00, v01);
            *(__half2*)(es0 + 8 * SK + col) = __floats2half2_rn(v10, v11);
            r0sum += v00 + v01; r1sum += v10 + v11;
            cloc[nj][0] += v00 + v10; cloc[nj][1] += v01 + v11;
        }
        r0sum += __shfl_xor_sync(0xffffffffu, r0sum, 1);
        r0sum += __shfl_xor_sync(0xffffffffu, r0sum, 2);
        r1sum += __shfl_xor_sync(0xffffffffu, r1sum, 1);
        r1sum += __shfl_xor_sync(0xffffffffu, r1sum, 2);
        if ((lane & 3) == 0) {
            rs[wc * 256 + r0] = r0sum;
            rs[wc * 256 + r0 + 8] = r1sum;
        }
    }
#pragma unroll
    for (int nj = 0; nj < 4; nj++)
#pragma unroll
        for (int k = 0; k < 2; k++) {
            float v = cloc[nj][k];
            v += __shfl_xor_sync(0xffffffffu, v, 4);
            v += __shfl_xor_sync(0xffffffffu, v, 8);
            v += __shfl_xor_sync(0xffffffffu, v, 16);
            if (lane < 4) cs[wr * 128 + wc * 32 + nj * 8 + lane * 2 + k] = v;
        }
    __syncthreads();

    // coalesced E write-out: warp = 8 rows x 256B contiguous
    {
        const int er = t >> 2;            // 0..127
        const int ec = (t & 3) * 32;      // half offset in row
#pragma unroll
        for (int g = 0; g < 2; g++) {
            const int row = g * 128 + er;
            const uint4* srow = (const uint4*)(As + row * SK + ec);
            uint4* gdst = (uint4*)(g_E16 + (size_t)(batch * LL + l0 + row) * LL + m0 + ec);
#pragma unroll
            for (int q = 0; q < 4; q++) gdst[q] = srow[q];
        }
    }
    if (t < 256) {
        g_Rp[blockIdx.x][batch * LL + l0 + t] =
            rs[t] + rs[256 + t] + rs[512 + t] + rs[768 + t];
    } else if (t < 384) {
        const int i = t - 256;
        g_Cp[blockIdx.y][batch * LL + m0 + i] =
            cs[i] + cs[128 + i] + cs[256 + i] + cs[384 + i];
    }
}

// ---------------- fused_C: 512 thr, C-reduce + invC + aTs scale + vmask ----
__global__ __launch_bounds__(512) void fused_C() {
    __shared__ float sInv[128];
    const int mt = blockIdx.x * 128, batch = blockIdx.y;
    const int t = threadIdx.x;
    if (t < 128) {
        float s = 0.f;
#pragma unroll
        for (int q = 0; q < 4; q++) s += g_Cp[q][batch * LL + mt + t];
        g_C[batch * LL + mt + t] = s;
        sInv[t] = (s > 0.f) ? (1.f / s) : 0.f;
    }
    __syncthreads();
    const int d = t >> 2, mh = (t & 3) * 32;
    const size_t off = (size_t)(batch * HH + d) * LL + mt + mh;
    const uint4* src = (const uint4*)(g_aT16 + off);
    uint4* dst = (uint4*)(g_aTs16 + off);
    float vpart = 0.f;
#pragma unroll
    for (int q = 0; q < 4; q++) {
        uint4 v = src[q];
        __half2* h = (__half2*)&v;
#pragma unroll
        for (int k = 0; k < 4; k++) {
            float2 f = __half22float2(h[k]);
            const int ml = mh + q * 8 + k * 2;
            const float i0 = sInv[ml], i1 = sInv[ml + 1];
            vpart += (i0 == 0.f ? f.x : 0.f) + (i1 == 0.f ? f.y : 0.f);
            h[k] = __floats2half2_rn(f.x * i0, f.y * i1);
        }
        dst[q] = v;
    }
    vpart += __shfl_xor_sync(0xffffffffu, vpart, 1);
    vpart += __shfl_xor_sync(0xffffffffu, vpart, 2);
    if ((t & 3) == 0) g_vp[blockIdx.x][batch * HH + d] = vpart;
}

// ---------------- K3: dual feature GEMMs, 512 thr, 4x4 warp grid -----------
__global__ __launch_bounds__(512) void k3_feat(float* __restrict__ out) {
    extern __shared__ char dsm[];
    __half* S = (__half*)dsm;                       // 2 stages x SSTRIDE halfs
    float* smeanb = (float*)(S + 2 * SSTRIDE);
    float* svmask = smeanb + 128;
    float* sR     = svmask + 128;                   // 128 floats

    const int batch = blockIdx.y, l0 = blockIdx.x * 128;
    const int t = threadIdx.x, lane = t & 31, w = t >> 5;
    const int wr = w >> 2, wc = w & 3;              // 4x4 warp grid: 32l x 32d
    const uint32_t sbase = smem_u32(S);

    if (t < 128) {
        float s = 0.f;
#pragma unroll
        for (int q = 0; q < 8; q++) s += g_Rp[q][batch * LL + l0 + t];
        sR[t] = s;
    } else if (t < 256) {
        const int d = t - 128;
        float sb = 0.f, sv = 0.f;
#pragma unroll
        for (int q = 0; q < 8; q++) {
            sb += g_mbp[q][batch * HH + d];
            sv += g_vp[q][batch * HH + d];
        }
        smeanb[d] = sb;
        svmask[d] = sv;
    }

    const int row = t >> 2, kh = (t & 3) * 32;
    const __half* eg = g_E16   + ((size_t)(batch * LL + l0 + row)) * LL + kh;
    const __half* bg = g_bT16  + ((size_t)(batch * HH + row)) * LL + kh;
    const __half* ag = g_aTs16 + ((size_t)(batch * HH + row)) * LL + kh;
    const uint32_t sdst = sbase + (row * SK + kh) * 2;

    {
#pragma unroll
        for (int j = 0; j < 4; j++) {
            CP_ASYNC16(sdst + j * 16,                    eg + j * 8);
            CP_ASYNC16(sdst + 128 * SK * 2 + j * 16,     bg + j * 8);
            CP_ASYNC16(sdst + 256 * SK * 2 + j * 16,     ag + j * 8);
        }
        CP_COMMIT();
    }

    float acc_a[2][4][4], acc_b[2][4][4];
#pragma unroll
    for (int i = 0; i < 2; i++)
#pragma unroll
        for (int j = 0; j < 4; j++)
#pragma unroll
            for (int k = 0; k < 4; k++) { acc_a[i][j][k] = 0.f; acc_b[i][j][k] = 0.f; }

    const uint32_t eoff = sbase + ((wr * 32 + (lane & 15)) * SK + (lane >> 4) * 8) * 2;
    const uint32_t woff = sbase + ((wc * 32 + (lane & 15)) * SK + (lane >> 4) * 8) * 2;

    for (int mc = 0; mc < 8; mc++) {
        if (mc < 7) {
            const uint32_t nb = ((mc + 1) & 1) * SSTRIDE * 2;
            const int m1 = (mc + 1) * 128;
#pragma unroll
            for (int j = 0; j < 4; j++) {
                CP_ASYNC16(sdst + nb + j * 16,                eg + m1 + j * 8);
                CP_ASYNC16(sdst + nb + 128 * SK * 2 + j * 16, bg + m1 + j * 8);
                CP_ASYNC16(sdst + nb + 256 * SK * 2 + j * 16, ag + m1 + j * 8);
            }
            CP_COMMIT();
            asm volatile("cp.async.wait_group 1;");
        } else {
            asm volatile("cp.async.wait_group 0;");
        }
        __syncthreads();

        const uint32_t sb_ = (mc & 1) * SSTRIDE * 2;
        const uint32_t eaddr = eoff + sb_;
        const uint32_t baddr = woff + sb_ + 128 * SK * 2;
        const uint32_t aaddr = woff + sb_ + 256 * SK * 2;
#pragma unroll
        for (int c = 0; c < 8; c++) {
            uint32_t ev[2][4], bvb[2][4], bva[2][4];
#pragma unroll
            for (int mi = 0; mi < 2; mi++)
                LDSM4(ev[mi][0], ev[mi][1], ev[mi][2], ev[mi][3],
                      eaddr + (mi * 16 * SK + c * 16) * 2);
#pragma unroll
            for (int nh = 0; nh < 2; nh++) {
                LDSM4(bvb[nh][0], bvb[nh][1], bvb[nh][2], bvb[nh][3],
                      baddr + (nh * 16 * SK + c * 16) * 2);
                LDSM4(bva[nh][0], bva[nh][1], bva[nh][2], bva[nh][3],
                      aaddr + (nh * 16 * SK + c * 16) * 2);
            }
#pragma unroll
            for (int mi = 0; mi < 2; mi++)
#pragma unroll
                for (int nj = 0; nj < 4; nj++) {
                    mma_16816(acc_a[mi][nj], ev[mi], bvb[nj >> 1][nj & 1], bvb[nj >> 1][(nj & 1) + 2]);
                    mma_16816(acc_b[mi][nj], ev[mi], bva[nj >> 1][nj & 1], bva[nj >> 1][(nj & 1) + 2]);
                }
        }
        __syncthreads();
    }

    const size_t FB = (size_t)BB * LL * HH;
    const float INV = 1.f / 1024.f;
#pragma unroll
    for (int mi = 0; mi < 2; mi++) {
        const int r0 = wr * 32 + mi * 16 + (lane >> 2);
        const int g0 = batch * LL + l0 + r0;
        const float rv0 = sR[r0], rv1 = sR[r0 + 8];
        const float sc0 = (rv0 > 0.f) ? (1.f / rv0) : 0.f;
        const float sc1 = (rv1 > 0.f) ? (1.f / rv1) : 0.f;
        const bool u0 = !(rv0 > 0.f), u1 = !(rv1 > 0.f);
        float* oa0 = out + (size_t)g0 * HH;
        float* oa1 = oa0 + (size_t)8 * HH;
        float* ob0 = oa0 + FB;
        float* ob1 = oa1 + FB;
#pragma unroll
        for (int nj = 0; nj < 4; nj++) {
            const int col = wc * 32 + nj * 8 + (lane & 3) * 2;
            const float mb0 = smeanb[col] * INV, mb1 = smeanb[col + 1] * INV;
            const float vm0 = svmask[col] * INV, vm1 = svmask[col + 1] * INV;
            float* ca = acc_a[mi][nj];
            float* cb = acc_b[mi][nj];
            float2 va0 = { u0 ? mb0 : ca[0] * sc0, u0 ? mb1 : ca[1] * sc0 };
            float2 va1 = { u1 ? mb0 : ca[2] * sc1, u1 ? mb1 : ca[3] * sc1 };
            float2 vb0 = { cb[0] + vm0, cb[1] + vm1 };
            float2 vb1 = { cb[2] + vm0, cb[3] + vm1 };
            *(float2*)(oa0 + col) = va0;
            *(float2*)(oa1 + col) = va1;
            *(float2*)(ob0 + col) = vb0;
            *(float2*)(ob1 + col) = vb1;
        }
    }
}

// ---------------- launch ----------------------------------------------------
extern "C" void kernel_launch(void* const* d_in, const int* in_sizes, int n_in,
                              void* d_out, int out_size) {
    const float* a    = (const float*)d_in[0];
    const float* b    = (const float*)d_in[1];
    const int*   ma   = (const int*)d_in[2];
    const int*   mb   = (const int*)d_in[3];
    const float* temp = (const float*)d_in[4];
    float* out = (float*)d_out;

    const int K1_SMEM = 384 * SK * 2 + 512 + 4096 + 2048 + 1024; // 112128
    const int K3_SMEM = 2 * SSTRIDE * 2 + 2048;                  // 210944
    cudaFuncSetAttribute(k1_scores, cudaFuncAttributeMaxDynamicSharedMemorySize, K1_SMEM);
    cudaFuncSetAttribute(k3_feat,   cudaFuncAttributeMaxDynamicSharedMemorySize, K3_SMEM);

    conv16<<<2048, 256>>>(a, b);                               // launch 0
    transpose_ab<<<dim3(8, BB, 2), 256>>>();                   // launch 1
    k1_scores<<<dim3(8, 4, BB), 512, K1_SMEM>>>(ma, mb, temp); // launch 2
    fused_C<<<dim3(8, BB), 512>>>();                           // launch 3
    k3_feat<<<dim3(8, BB), 512, K3_SMEM>>>(out);               // launch 4
}